// round 1
// baseline (speedup 1.0000x reference)
#include <cuda_runtime.h>
#include <cstdint>

// Problem constants
#define BB    128
#define LL    9
#define KK    3
#define PP    1680
#define CIN   256
#define COUT  256
// Z: (B*L, K*COUT) = (1152, 768)
#define ZR    1152
#define ZC    768

// Scratch (device globals: allocation-free)
__device__ float g_Z[ZR * ZC];      // 3.4 MB
__device__ int   g_codes[PP];

// ---------------------------------------------------------------------------
// Kernel 0: decode mask M (K,P,L) -> packed base-3 codes per permutation.
// code = c0 | c1<<8 | c2<<16, c_g = a[3g] + 3*a[3g+1] + 9*a[3g+2]
// ---------------------------------------------------------------------------
__global__ void decode_codes(const float* __restrict__ M) {
    int p = blockIdx.x * 256 + threadIdx.x;
    if (p >= PP) return;
    const int PL = PP * LL;
    int c[3] = {0, 0, 0};
    const int w3[3] = {1, 3, 9};
#pragma unroll
    for (int l = 0; l < LL; l++) {
        float m1 = M[PL + p * LL + l];
        float m2 = M[2 * PL + p * LL + l];
        int a = (m1 > 0.5f) ? 1 : ((m2 > 0.5f) ? 2 : 0);
        c[l / 3] += a * w3[l % 3];
    }
    g_codes[p] = c[0] | (c[1] << 8) | (c[2] << 16);
}

// ---------------------------------------------------------------------------
// Kernel 1: Z[r,j] = sum_c X[r,c] * Wm[j,c]
// X: (1152,256) row-major; Wm: (768,256) row-major (== W[k,o,c] flattened)
// 64x64 tile per block, K-chunks of 64, transposed smem tiles for
// conflict-free compute reads. 256 threads, 4x4 register tile/thread.
// ---------------------------------------------------------------------------
__global__ void __launch_bounds__(256) gemm_z(const float* __restrict__ X,
                                              const float* __restrict__ Wm) {
    __shared__ float sXt[64][68];   // [c][r], pad keeps 16B alignment (68%4==0)
    __shared__ float sWt[64][68];   // [c][j]

    const int t  = threadIdx.x;
    const int rb = blockIdx.x * 64;   // row base (18 blocks)
    const int jb = blockIdx.y * 64;   // col base (12 blocks)

    const int c4 = t & 15;   // which float4 along c during loads
    const int rr = t >> 4;   // 0..15

    float acc[4][4];
#pragma unroll
    for (int i = 0; i < 4; i++)
#pragma unroll
        for (int j = 0; j < 4; j++) acc[i][j] = 0.0f;

    const int row0 = (t >> 4) * 4;  // 0..60
    const int col0 = (t & 15) * 4;  // 0..60

    for (int kc = 0; kc < CIN; kc += 64) {
#pragma unroll
        for (int i = 0; i < 4; i++) {
            int r = rr + i * 16;
            float4 v = *(const float4*)&X[(rb + r) * CIN + kc + c4 * 4];
            sXt[c4 * 4 + 0][r] = v.x;
            sXt[c4 * 4 + 1][r] = v.y;
            sXt[c4 * 4 + 2][r] = v.z;
            sXt[c4 * 4 + 3][r] = v.w;
            float4 w = *(const float4*)&Wm[(jb + r) * CIN + kc + c4 * 4];
            sWt[c4 * 4 + 0][r] = w.x;
            sWt[c4 * 4 + 1][r] = w.y;
            sWt[c4 * 4 + 2][r] = w.z;
            sWt[c4 * 4 + 3][r] = w.w;
        }
        __syncthreads();

#pragma unroll
        for (int c = 0; c < 64; c++) {
            float4 xa = *(const float4*)&sXt[c][row0];  // broadcast across lanes
            float4 wb = *(const float4*)&sWt[c][col0];  // conflict-free
            acc[0][0] += xa.x * wb.x; acc[0][1] += xa.x * wb.y;
            acc[0][2] += xa.x * wb.z; acc[0][3] += xa.x * wb.w;
            acc[1][0] += xa.y * wb.x; acc[1][1] += xa.y * wb.y;
            acc[1][2] += xa.y * wb.z; acc[1][3] += xa.y * wb.w;
            acc[2][0] += xa.z * wb.x; acc[2][1] += xa.z * wb.y;
            acc[2][2] += xa.z * wb.z; acc[2][3] += xa.z * wb.w;
            acc[3][0] += xa.w * wb.x; acc[3][1] += xa.w * wb.y;
            acc[3][2] += xa.w * wb.z; acc[3][3] += xa.w * wb.w;
        }
        __syncthreads();
    }

    float4* Z4 = (float4*)g_Z;
#pragma unroll
    for (int i = 0; i < 4; i++) {
        float4 v = make_float4(acc[i][0], acc[i][1], acc[i][2], acc[i][3]);
        Z4[(rb + row0 + i) * (ZC / 4) + (jb + col0) / 4] = v;
    }
}

// ---------------------------------------------------------------------------
// Kernel 2: per (b, channel-half, p-chunk) block:
//   build 3 partial-sum tables T_g[27][128ch] in smem (from Z in L2),
//   then each output float4 = T0[c0] + T1[c1] + T2[c2], streamed to GMEM.
// grid = (5 p-chunks of 336, 2 channel halves, 128 b), 256 threads.
// smem: 81*32 float4 (41.5 KB) + 336 codes -> 5 CTAs/SM.
// ---------------------------------------------------------------------------
#define PCHUNK 336
#define NCHUNK 5

__global__ void __launch_bounds__(256) perm_combine(float* __restrict__ out) {
    __shared__ float4 sT4[81 * 32];
    __shared__ int sCodes[PCHUNK];

    const int t     = threadIdx.x;
    const int chunk = blockIdx.x;   // 0..4
    const int h     = blockIdx.y;   // channel half 0..1
    const int b     = blockIdx.z;   // 0..127
    const int pbase = chunk * PCHUNK;

    // ---- build tables ----
    const float4* Z4 = (const float4*)g_Z;
    const int zb = b * LL * KK * (COUT / 4) + h * 32;
    for (int i = t; i < 81 * 32; i += 256) {
        int o4 = i & 31;
        int cc = i >> 5;          // 0..80 = g*27 + c
        int g  = cc / 27;
        int c  = cc - g * 27;
        int d0 = c % 3, d1 = (c / 3) % 3, d2 = c / 9;
        int l  = 3 * g;
        float4 v0 = Z4[zb + ((l + 0) * 3 + d0) * (COUT / 4) + o4];
        float4 v1 = Z4[zb + ((l + 1) * 3 + d1) * (COUT / 4) + o4];
        float4 v2 = Z4[zb + ((l + 2) * 3 + d2) * (COUT / 4) + o4];
        float4 s;
        s.x = v0.x + v1.x + v2.x;
        s.y = v0.y + v1.y + v2.y;
        s.z = v0.z + v1.z + v2.z;
        s.w = v0.w + v1.w + v2.w;
        sT4[i] = s;
    }
    for (int i = t; i < PCHUNK; i += 256) sCodes[i] = g_codes[pbase + i];
    __syncthreads();

    // ---- combine + stream out ----
    const int o4 = t & 31;   // float4 index within 128-ch half
    const int pw = t >> 5;   // 0..7 (p within iteration group)
    float4* out4 = (float4*)out;
    const int obase = (b * PP + pbase) * (COUT / 4) + h * 32 + o4;

#pragma unroll 2
    for (int it = 0; it < PCHUNK / 8; it++) {
        int po   = it * 8 + pw;
        int code = sCodes[po];
        int c0 = code & 0xFF;
        int c1 = (code >> 8) & 0xFF;
        int c2 = (code >> 16) & 0xFF;
        float4 a  = sT4[c0 * 32 + o4];
        float4 bb = sT4[(27 + c1) * 32 + o4];
        float4 cv = sT4[(54 + c2) * 32 + o4];
        float4 r;
        r.x = a.x + bb.x + cv.x;
        r.y = a.y + bb.y + cv.y;
        r.z = a.z + bb.z + cv.z;
        r.w = a.w + bb.w + cv.w;
        __stcs(&out4[obase + po * (COUT / 4)], r);
    }
}

// ---------------------------------------------------------------------------
extern "C" void kernel_launch(void* const* d_in, const int* in_sizes, int n_in,
                              void* d_out, int out_size) {
    (void)in_sizes; (void)n_in; (void)out_size;
    const float* x = (const float*)d_in[0];  // (128, 9, 256)
    const float* W = (const float*)d_in[1];  // (3, 256, 256) -> (768, 256)
    const float* M = (const float*)d_in[2];  // (3, 1680, 9)
    float* out = (float*)d_out;              // (128, 1680, 256)

    decode_codes<<<(PP + 255) / 256, 256>>>(M);
    gemm_z<<<dim3(ZR / 64, ZC / 64), 256>>>(x, W);
    perm_combine<<<dim3(NCHUNK, 2, BB), 256>>>(out);
}